// round 12
// baseline (speedup 1.0000x reference)
#include <cuda_runtime.h>
#include <math.h>

#define Bz 8
#define Cc 64
#define Nn 32768
#define Rr 32
#define R3v (Rr*Rr*Rr)

// ---------------- device scratch (no allocations allowed) ----------------
__device__ __align__(16) float g_acc[(size_t)Bz*R3v*Cc];   // voxel accum -> vox (in place)
__device__ __align__(16) float g_cnt[Bz*R3v];
__device__ __align__(16) float g_c1 [(size_t)Bz*R3v*Cc];   // conv1 out (channels-last)
__device__ __align__(16) float g_c2 [(size_t)Bz*R3v*Cc];   // conv2 out (channels-last)
__device__ __align__(16) float g_featT[(size_t)Bz*Nn*Cc];  // features transposed [b][n][c]
__device__ __align__(16) float g_w1T[27*64*64];            // [tap][ci][co]
__device__ __align__(16) float g_w2T[27*64*64];
__device__ __align__(16) float g_mlpT[64*64];              // [c][o]
__device__ float g_s1[64], g_b1[64], g_s2[64], g_b2[64], g_sp[64], g_bp[64];
__device__ float g_mean[Bz*4];
__device__ float g_scl[Bz];

// ---------------- f32x2 helpers (FFMA2: 2x fp32 FMA throughput) ----------
__device__ __forceinline__ unsigned long long pack2(float x, float y) {
    unsigned long long r;
    asm("mov.b64 %0, {%1, %2};" : "=l"(r) : "f"(x), "f"(y));
    return r;
}
__device__ __forceinline__ void fma2(unsigned long long& d, unsigned long long a, unsigned long long b) {
    asm("fma.rn.f32x2 %0, %1, %2, %0;" : "+l"(d) : "l"(a), "l"(b));
}
__device__ __forceinline__ float2 unpack2(unsigned long long v) {
    float2 r;
    asm("mov.b64 {%0, %1}, %2;" : "=f"(r.x), "=f"(r.y) : "l"(v));
    return r;
}

// ---------------- prep: fold BN into scale/bias, transpose mlp ----------
__global__ void prep_params(
    const float* __restrict__ conv1_b, const float* __restrict__ bn1_g, const float* __restrict__ bn1_b,
    const float* __restrict__ bn1_m,  const float* __restrict__ bn1_v,
    const float* __restrict__ conv2_b, const float* __restrict__ bn2_g, const float* __restrict__ bn2_b,
    const float* __restrict__ bn2_m,  const float* __restrict__ bn2_v,
    const float* __restrict__ mlp_w,  const float* __restrict__ mlp_b,
    const float* __restrict__ bnp_g,  const float* __restrict__ bnp_b,
    const float* __restrict__ bnp_m,  const float* __restrict__ bnp_v)
{
    int c = threadIdx.x;
    if (c < 64) {
        float s1 = bn1_g[c] * rsqrtf(bn1_v[c] + 1e-4f);
        g_s1[c] = s1;  g_b1[c] = (conv1_b[c] - bn1_m[c]) * s1 + bn1_b[c];
        float s2 = bn2_g[c] * rsqrtf(bn2_v[c] + 1e-4f);
        g_s2[c] = s2;  g_b2[c] = (conv2_b[c] - bn2_m[c]) * s2 + bn2_b[c];
        float sp = bnp_g[c] * rsqrtf(bnp_v[c] + 1e-4f);
        g_sp[c] = sp;  g_bp[c] = (mlp_b[c] - bnp_m[c]) * sp + bnp_b[c];
        for (int o = 0; o < 64; ++o) g_mlpT[c*64 + o] = mlp_w[o*64 + c];
    }
}

// ---------------- weight transpose [co][ci][27] -> [t][ci][co] -----------
__global__ void transpose_w(const float* __restrict__ w1, const float* __restrict__ w2)
{
    int e = blockIdx.x * 256 + threadIdx.x;
    if (e < 110592) {
        int co = e & 63, ci = (e >> 6) & 63, t = e >> 12;
        g_w1T[e] = w1[(co*64 + ci)*27 + t];
    } else if (e < 221184) {
        int o = e - 110592;
        int co = o & 63, ci = (o >> 6) & 63, t = o >> 12;
        g_w2T[o] = w2[(co*64 + ci)*27 + t];
    }
}

// ---------------- features [b][c][n] -> [b][n][c] ------------------------
__global__ void transpose_feat(const float* __restrict__ feat)
{
    __shared__ float t[32][33];
    int n0 = blockIdx.x * 32, c0 = blockIdx.y * 32, b = blockIdx.z;
    int tx = threadIdx.x, ty = threadIdx.y;
#pragma unroll
    for (int j = 0; j < 32; j += 8)
        t[ty + j][tx] = feat[((size_t)b*64 + c0 + ty + j)*Nn + n0 + tx];
    __syncthreads();
#pragma unroll
    for (int j = 0; j < 32; j += 8)
        g_featT[((size_t)b*Nn + n0 + ty + j)*64 + c0 + tx] = t[tx][ty + j];
}

// ---------------- per-batch mean + max-norm ------------------------------
__global__ void reduce_coords(const float* __restrict__ coords)
{
    __shared__ float sm[1024];
    int b = blockIdx.x, tid = threadIdx.x;
    const float* px = coords + (size_t)b*3*Nn;
    const float* py = px + Nn;
    const float* pz = py + Nn;
    float sx = 0.f, sy = 0.f, sz = 0.f;
    for (int i = tid; i < Nn; i += 1024) { sx += px[i]; sy += py[i]; sz += pz[i]; }

    sm[tid] = sx; __syncthreads();
    for (int s = 512; s > 0; s >>= 1) { if (tid < s) sm[tid] += sm[tid + s]; __syncthreads(); }
    float mx = sm[0] * (1.f / Nn); __syncthreads();

    sm[tid] = sy; __syncthreads();
    for (int s = 512; s > 0; s >>= 1) { if (tid < s) sm[tid] += sm[tid + s]; __syncthreads(); }
    float my = sm[0] * (1.f / Nn); __syncthreads();

    sm[tid] = sz; __syncthreads();
    for (int s = 512; s > 0; s >>= 1) { if (tid < s) sm[tid] += sm[tid + s]; __syncthreads(); }
    float mz = sm[0] * (1.f / Nn); __syncthreads();

    float mm = 0.f;
    for (int i = tid; i < Nn; i += 1024) {
        float dx = px[i] - mx, dy = py[i] - my, dz = pz[i] - mz;
        mm = fmaxf(mm, dx*dx + dy*dy + dz*dz);
    }
    sm[tid] = mm; __syncthreads();
    for (int s = 512; s > 0; s >>= 1) { if (tid < s) sm[tid] = fmaxf(sm[tid], sm[tid + s]); __syncthreads(); }
    if (tid == 0) {
        g_mean[b*4 + 0] = mx; g_mean[b*4 + 1] = my; g_mean[b*4 + 2] = mz;
        g_scl[b] = (float)Rr / (2.f * sqrtf(sm[0]) * (1.f + 1e-6f));
    }
}

// ---------------- zero acc + cnt -----------------------------------------
__global__ void zero_kernel()
{
    int i = blockIdx.x * 256 + threadIdx.x;       // 16384*256 = 4194304
    float4 z = make_float4(0.f, 0.f, 0.f, 0.f);
    reinterpret_cast<float4*>(g_acc)[i] = z;      // Bz*R3v*16 = 4194304 exactly
    if (i < Bz*R3v/4) reinterpret_cast<float4*>(g_cnt)[i] = z;
}

// ---------------- trilinear scatter (warp per point) ----------------------
__global__ __launch_bounds__(256)
void scatter_kernel(const float* __restrict__ coords)
{
    int tid = threadIdx.x;
    int warp = tid >> 5, lane = tid & 31;
    int pid = blockIdx.x * 8 + warp;
    int b = pid >> 15, n = pid & (Nn - 1);

    float mx = g_mean[b*4+0], my = g_mean[b*4+1], mz = g_mean[b*4+2];
    float s  = g_scl[b];
    float cx = coords[((size_t)b*3 + 0)*Nn + n];
    float cy = coords[((size_t)b*3 + 1)*Nn + n];
    float cz = coords[((size_t)b*3 + 2)*Nn + n];
    float vx = fminf(fmaxf((cx - mx)*s + 16.f, 0.f), 31.f);
    float vy = fminf(fmaxf((cy - my)*s + 16.f, 0.f), 31.f);
    float vz = fminf(fmaxf((cz - mz)*s + 16.f, 0.f), 31.f);
    float fx = floorf(vx), fy = floorf(vy), fz = floorf(vz);
    int ix = (int)fx, iy = (int)fy, iz = (int)fz;
    float frx = vx - fx, fry = vy - fy, frz = vz - fz;

    float f0 = g_featT[(size_t)pid*64 + lane];
    float f1 = g_featT[(size_t)pid*64 + 32 + lane];

#pragma unroll
    for (int k = 0; k < 8; ++k) {
        int dx = k >> 2, dy = (k >> 1) & 1, dz = k & 1;
        int xi = min(ix + dx, 31), yi = min(iy + dy, 31), zi = min(iz + dz, 31);
        float w = (dx ? frx : 1.f - frx) * (dy ? fry : 1.f - fry) * (dz ? frz : 1.f - frz);
        size_t vb = (size_t)b*R3v + ((xi*32 + yi)*32 + zi);
        float* ap = g_acc + vb*64;
        atomicAdd(ap + lane,      w * f0);
        atomicAdd(ap + lane + 32, w * f1);
        if (lane == 0) atomicAdd(&g_cnt[vb], w);
    }
}

// ---------------- vox = acc / max(cnt, 1e-8) (in place) -------------------
__global__ void normalize_kernel()
{
    int i = blockIdx.x * 256 + threadIdx.x;   // 4194304 float4
    int v = i >> 4;
    float c = g_cnt[v];
    float r = 1.f / fmaxf(c, 1e-8f);
    float4 f = reinterpret_cast<float4*>(g_acc)[i];
    f.x *= r; f.y *= r; f.z *= r; f.w *= r;
    reinterpret_cast<float4*>(g_acc)[i] = f;
}

// ---------------- 3x3x3 conv + BN + LeakyReLU (channels-last) -------------
// Block: (b, x, y-slab of 8) -> 8y * 32z voxels x 64 co. Thread: 8 vox x 8 co,
// f32x2 packed accumulators -> FFMA2-pipe-bound.
__global__ __launch_bounds__(256, 2)
void conv3d_kernel(const float* __restrict__ in, float* __restrict__ out,
                   const float* __restrict__ wT,
                   const float* __restrict__ sc, const float* __restrict__ bi)
{
    __shared__ __align__(16) float s_in[3*10*34*4];   // [dx][y:10][z:34][ci:4]
    __shared__ __align__(16) float s_w [27*4*64];     // [t][ci][co]

    const int tid = threadIdx.x;
    const int b = blockIdx.z, x = blockIdx.y, y0 = blockIdx.x * 8;
    const int vg = tid >> 3;     // z = vg (0..31)
    const int cg = tid & 7;      // co = p*16 + cg*2 + {0,1}

    unsigned long long acc[8][4];
#pragma unroll
    for (int k = 0; k < 8; ++k)
#pragma unroll
        for (int p = 0; p < 4; ++p) acc[k][p] = 0ull;

    for (int ch = 0; ch < 16; ++ch) {        // ci chunks of 4
        __syncthreads();
#pragma unroll 1
        for (int e = tid; e < 3*10*34*4; e += 256) {
            int ci = e & 3;
            int zi = (e >> 2) % 34;
            int r  = (e >> 2) / 34;
            int yy = r % 10;
            int dx = r / 10;
            int xg = x + dx - 1, yg = y0 + yy - 1, zg = zi - 1;
            float v = 0.f;
            if ((unsigned)xg < 32u && (unsigned)yg < 32u && (unsigned)zg < 32u)
                v = in[((((size_t)b*32 + xg)*32 + yg)*32 + zg)*64 + (ch << 2) + ci];
            s_in[e] = v;
        }
#pragma unroll 1
        for (int e = tid; e < 27*4*64; e += 256) {
            int co = e & 63;
            int ci = (e >> 6) & 3;
            int t  = e >> 8;
            s_w[e] = wT[((size_t)(t*64 + (ch << 2) + ci))*64 + co];
        }
        __syncthreads();
#pragma unroll 1
        for (int t = 0; t < 27; ++t) {
            int dx = t / 9; int rr = t - dx*9; int dy = rr / 3; int dz = rr - dy*3;
            const float* ib = s_in + ((dx*10 + dy)*34 + vg + dz)*4;
            const float* wb = s_w + t*256 + (cg << 1);
#pragma unroll
            for (int ci = 0; ci < 4; ++ci) {
                unsigned long long w0 = *(const unsigned long long*)(wb + ci*64);
                unsigned long long w1 = *(const unsigned long long*)(wb + ci*64 + 16);
                unsigned long long w2 = *(const unsigned long long*)(wb + ci*64 + 32);
                unsigned long long w3 = *(const unsigned long long*)(wb + ci*64 + 48);
#pragma unroll
                for (int k = 0; k < 8; ++k) {
                    float a = ib[k*136 + ci];       // y step = 34*4 floats
                    unsigned long long a2 = pack2(a, a);
                    fma2(acc[k][0], a2, w0);
                    fma2(acc[k][1], a2, w1);
                    fma2(acc[k][2], a2, w2);
                    fma2(acc[k][3], a2, w3);
                }
            }
        }
    }
    // epilogue: BN fold + LeakyReLU(0.1), coalesced float2 stores
#pragma unroll
    for (int k = 0; k < 8; ++k) {
        size_t base = ((((size_t)b*32 + x)*32 + (y0 + k))*32 + vg)*64;
#pragma unroll
        for (int p = 0; p < 4; ++p) {
            int co = p*16 + (cg << 1);
            float2 v = unpack2(acc[k][p]);
            float r0 = v.x * sc[co]     + bi[co];
            float r1 = v.y * sc[co + 1] + bi[co + 1];
            r0 = r0 > 0.f ? r0 : 0.1f * r0;
            r1 = r1 > 0.f ? r1 : 0.1f * r1;
            *reinterpret_cast<float2*>(out + base + co) = make_float2(r0, r1);
        }
    }
}

// ---------------- devoxelize + point-MLP branch + output -------------------
__global__ __launch_bounds__(256)
void devox_kernel(const float* __restrict__ coords, float* __restrict__ out)
{
    __shared__ float s_mlpT[64*64];
    __shared__ float s_out[64][9];
    int tid = threadIdx.x;
#pragma unroll 1
    for (int e = tid; e < 4096; e += 256) s_mlpT[e] = g_mlpT[e];

    int warp = tid >> 5, lane = tid & 31;
    int pid0 = blockIdx.x * 8;
    int pid = pid0 + warp;
    int b = pid >> 15, n = pid & (Nn - 1);
    __syncthreads();

    float mx = g_mean[b*4+0], my = g_mean[b*4+1], mz = g_mean[b*4+2];
    float s  = g_scl[b];
    float cx = coords[((size_t)b*3 + 0)*Nn + n];
    float cy = coords[((size_t)b*3 + 1)*Nn + n];
    float cz = coords[((size_t)b*3 + 2)*Nn + n];
    float vx = fminf(fmaxf((cx - mx)*s + 16.f, 0.f), 31.f);
    float vy = fminf(fmaxf((cy - my)*s + 16.f, 0.f), 31.f);
    float vz = fminf(fmaxf((cz - mz)*s + 16.f, 0.f), 31.f);
    float fx = floorf(vx), fy = floorf(vy), fz = floorf(vz);
    int ix = (int)fx, iy = (int)fy, iz = (int)fz;
    float frx = vx - fx, fry = vy - fy, frz = vz - fz;

    // point branch: p[o] = relu(dot(mlp_w[o,:], feat) * sp + bp)
    float f0 = g_featT[(size_t)pid*64 + lane];
    float f1 = g_featT[(size_t)pid*64 + 32 + lane];
    float p0 = 0.f, p1 = 0.f;
#pragma unroll 1
    for (int c = 0; c < 64; ++c) {
        float fc = __shfl_sync(0xffffffffu, (c < 32) ? f0 : f1, c & 31);
        p0 = fmaf(s_mlpT[c*64 + lane],      fc, p0);
        p1 = fmaf(s_mlpT[c*64 + 32 + lane], fc, p1);
    }

    float d0 = 0.f, d1 = 0.f;
#pragma unroll
    for (int k = 0; k < 8; ++k) {
        int dx = k >> 2, dy = (k >> 1) & 1, dz = k & 1;
        int xi = min(ix + dx, 31), yi = min(iy + dy, 31), zi = min(iz + dz, 31);
        float w = (dx ? frx : 1.f - frx) * (dy ? fry : 1.f - fry) * (dz ? frz : 1.f - frz);
        const float* gp = g_c2 + ((size_t)b*R3v + ((xi*32 + yi)*32 + zi))*64;
        d0 = fmaf(w, gp[lane],      d0);
        d1 = fmaf(w, gp[lane + 32], d1);
    }
    p0 = fmaxf(fmaf(p0, g_sp[lane],      g_bp[lane]),      0.f);
    p1 = fmaxf(fmaf(p1, g_sp[lane + 32], g_bp[lane + 32]), 0.f);
    s_out[lane][warp]      = d0 + p0;
    s_out[lane + 32][warp] = d1 + p1;
    __syncthreads();

    int bb = pid0 >> 15;
    int n0 = pid0 & (Nn - 1);
#pragma unroll
    for (int e = tid; e < 512; e += 256) {
        int o = e >> 3, pi = e & 7;
        out[((size_t)bb*64 + o)*Nn + n0 + pi] = s_out[o][pi];
    }
}

// ---------------- launch ---------------------------------------------------
extern "C" void kernel_launch(void* const* d_in, const int* in_sizes, int n_in,
                              void* d_out, int out_size)
{
    const float* features = (const float*)d_in[0];
    const float* coords   = (const float*)d_in[1];
    const float* conv1_w  = (const float*)d_in[2];
    const float* conv1_b  = (const float*)d_in[3];
    const float* bn1_g    = (const float*)d_in[4];
    const float* bn1_b    = (const float*)d_in[5];
    const float* bn1_m    = (const float*)d_in[6];
    const float* bn1_v    = (const float*)d_in[7];
    const float* conv2_w  = (const float*)d_in[8];
    const float* conv2_b  = (const float*)d_in[9];
    const float* bn2_g    = (const float*)d_in[10];
    const float* bn2_b    = (const float*)d_in[11];
    const float* bn2_m    = (const float*)d_in[12];
    const float* bn2_v    = (const float*)d_in[13];
    const float* mlp_w    = (const float*)d_in[14];
    const float* mlp_b    = (const float*)d_in[15];
    const float* bnp_g    = (const float*)d_in[16];
    const float* bnp_b    = (const float*)d_in[17];
    const float* bnp_m    = (const float*)d_in[18];
    const float* bnp_v    = (const float*)d_in[19];
    float* out = (float*)d_out;

    void *p_acc, *p_c1, *p_c2, *p_w1T, *p_w2T, *p_s1, *p_b1, *p_s2, *p_b2;
    cudaGetSymbolAddress(&p_acc, g_acc);
    cudaGetSymbolAddress(&p_c1,  g_c1);
    cudaGetSymbolAddress(&p_c2,  g_c2);
    cudaGetSymbolAddress(&p_w1T, g_w1T);
    cudaGetSymbolAddress(&p_w2T, g_w2T);
    cudaGetSymbolAddress(&p_s1,  g_s1);
    cudaGetSymbolAddress(&p_b1,  g_b1);
    cudaGetSymbolAddress(&p_s2,  g_s2);
    cudaGetSymbolAddress(&p_b2,  g_b2);

    prep_params<<<1, 64>>>(conv1_b, bn1_g, bn1_b, bn1_m, bn1_v,
                           conv2_b, bn2_g, bn2_b, bn2_m, bn2_v,
                           mlp_w, mlp_b, bnp_g, bnp_b, bnp_m, bnp_v);
    transpose_w<<<864, 256>>>(conv1_w, conv2_w);
    transpose_feat<<<dim3(Nn/32, 2, Bz), dim3(32, 8)>>>(features);
    reduce_coords<<<Bz, 1024>>>(coords);
    zero_kernel<<<16384, 256>>>();
    scatter_kernel<<<(Bz*Nn)/8, 256>>>(coords);
    normalize_kernel<<<16384, 256>>>();
    conv3d_kernel<<<dim3(4, 32, Bz), 256>>>((const float*)p_acc, (float*)p_c1,
                                            (const float*)p_w1T, (const float*)p_s1, (const float*)p_b1);
    conv3d_kernel<<<dim3(4, 32, Bz), 256>>>((const float*)p_c1, (float*)p_c2,
                                            (const float*)p_w2T, (const float*)p_s2, (const float*)p_b2);
    devox_kernel<<<(Bz*Nn)/8, 256>>>(coords, out);
    cudaMemcpyAsync(out + (size_t)Bz*64*Nn, coords,
                    (size_t)Bz*3*Nn*sizeof(float), cudaMemcpyDeviceToDevice);
}